// round 11
// baseline (speedup 1.0000x reference)
#include <cuda_runtime.h>
#include <cuda_bf16.h>

#define G 8
#define THREADS 256
#define NBLK (8192 / G)

typedef unsigned long long f32x2_t;

__device__ __forceinline__ f32x2_t fma2(f32x2_t a, f32x2_t b, f32x2_t c) {
    f32x2_t d;
    asm("fma.rn.f32x2 %0, %1, %2, %3;" : "=l"(d) : "l"(a), "l"(b), "l"(c));
    return d;
}
__device__ __forceinline__ f32x2_t pk2(float lo, float hi) {
    f32x2_t d;
    asm("mov.b64 %0, {%1, %2};" : "=l"(d) : "f"(lo), "f"(hi));
    return d;
}
__device__ __forceinline__ float2 upk(f32x2_t d) {
    float2 v;
    asm("mov.b64 {%0, %1}, %2;" : "=f"(v.x), "=f"(v.y) : "l"(d));
    return v;
}
__device__ __forceinline__ f32x2_t dup2(float v) { return pk2(v, v); }

// Binarized weights, repacked (16B-aligned).
__device__ __align__(16) float g_w1c[3 * 25 * 8];       // [cin][k][c8] (c<6 used)
__device__ __align__(16) float g_w2c[4 * 6 * 25 * 4];   // [cq][cin][k][c4]
__device__ __align__(16) float g_fw1t[400 * 120];       // [k][j]
__device__ __align__(16) float g_fw2t[120 * 84];        // [k][j]
__device__ __align__(16) float g_fw3t[84 * 10];         // [k][j]

__global__ void binarize_kernel(const float* __restrict__ w1,
                                const float* __restrict__ w2,
                                const float* __restrict__ fw1,
                                const float* __restrict__ fw2,
                                const float* __restrict__ fw3) {
    __shared__ float red[256];
    int t = threadIdx.x;
    const float* src = nullptr;
    int n = 0;
    switch (blockIdx.x) {
        case 0: src = w1;  n = 450;   break;
        case 1: src = w2;  n = 2400;  break;
        case 2: src = fw1; n = 48000; break;
        case 3: src = fw2; n = 10080; break;
        case 4: src = fw3; n = 840;   break;
    }
    float s = 0.0f;
    for (int i = t; i < n; i += 256) s += fabsf(src[i]);
    red[t] = s;
    __syncthreads();
    for (int o = 128; o > 0; o >>= 1) {
        if (t < o) red[t] += red[t + o];
        __syncthreads();
    }
    float scale = red[0] / (float)n;

    switch (blockIdx.x) {
        case 0:  // w1[o][cin][5][5] -> [cin][k][c8]
            for (int i = t; i < n; i += 256) {
                int o = i / 75, rem = i % 75, cin = rem / 25, k = rem % 25;
                g_w1c[(cin * 25 + k) * 8 + o] = (src[i] >= 0.0f) ? scale : -scale;
            }
            break;
        case 1:  // w2[o][cin][5][5] -> [cq][cin][k][c4]
            for (int i = t; i < n; i += 256) {
                int o = i / 150, rem = i % 150, cin = rem / 25, k = rem % 25;
                int cq = o >> 2, cl = o & 3;
                g_w2c[((cq * 6 + cin) * 25 + k) * 4 + cl] = (src[i] >= 0.0f) ? scale : -scale;
            }
            break;
        case 2:  // fc1 [120][400] -> [400][120]
            for (int i = t; i < n; i += 256) {
                int r = i / 400, c = i % 400;
                g_fw1t[c * 120 + r] = (src[i] >= 0.0f) ? scale : -scale;
            }
            break;
        case 3:  // fc2 [84][120] -> [120][84]
            for (int i = t; i < n; i += 256) {
                int r = i / 120, c = i % 120;
                g_fw2t[c * 84 + r] = (src[i] >= 0.0f) ? scale : -scale;
            }
            break;
        case 4:  // fc3 [10][84] -> [84][10]
            for (int i = t; i < n; i += 256) {
                int r = i / 84, c = i % 84;
                g_fw3t[c * 10 + r] = (src[i] >= 0.0f) ? scale : -scale;
            }
            break;
    }
}

extern __shared__ float smem[];

__global__ void __launch_bounds__(THREADS, 2)
fused_kernel(const float* __restrict__ x,
             const float* __restrict__ b1, const float* __restrict__ b2,
             const float* __restrict__ fb1, const float* __restrict__ fb2,
             const float* __restrict__ fb3,
             float* __restrict__ out) {
    // All activations stored as image-PAIR interleaved float2 (imgA, imgB).
    float2* const p1p = (float2*)smem;        // 4 pairs * 6c * 196    = 4704 float2
    float2* const h2p = p1p + 4704;           // 4 * 400               = 1600 float2
    float2* const a1p = h2p + 1600;           // 4 * 120               = 480 float2
    float2* const a2p = a1p + 480;            // 4 * 84                = 336 float2
    float* const w1s = (float*)(a2p + 336);   // 600
    float* const w2s = w1s + 600;             // 2400
    float* const b1s = w2s + 2400;            // 6
    float* const b2s = b1s + 6;               // 16

    const int tid = threadIdx.x;
    const int img0 = blockIdx.x * G;

    for (int i = tid; i < 600; i += THREADS)  w1s[i] = g_w1c[i];
    for (int i = tid; i < 2400; i += THREADS) w2s[i] = g_w2c[i];
    if (tid < 6)  b1s[tid] = b1[tid];
    if (tid < 16) b2s[tid] = b2[tid];
    __syncthreads();

    // ---- conv1 + relu + pool : thread = (img-pair, pooled px) ----
    for (int s = tid; s < 4 * 196; s += THREADS) {
        int ip = s / 196, p = s % 196;
        int py = p / 14, px = p % 14;
        const float* xa = x + (size_t)(img0 + ip * 2) * 3072 + py * 64 + px * 2;
        const float* xb = xa + 3072;

        #pragma unroll 1
        for (int cg = 0; cg < 2; cg++) {            // channel groups {0-2},{3-5}
            f32x2_t acc[3][4];
            #pragma unroll
            for (int c = 0; c < 3; c++)
                acc[c][0] = acc[c][1] = acc[c][2] = acc[c][3] = 0ULL;

            #pragma unroll 1
            for (int cin = 0; cin < 3; cin++) {
                f32x2_t wp[6][6];
                const float* ia = xa + cin * 1024;
                const float* ib = xb + cin * 1024;
                #pragma unroll
                for (int r = 0; r < 6; r++) {
                    float2 a0 = __ldg((const float2*)(ia + r * 32));
                    float2 a1 = __ldg((const float2*)(ia + r * 32 + 2));
                    float2 a2 = __ldg((const float2*)(ia + r * 32 + 4));
                    float2 c0 = __ldg((const float2*)(ib + r * 32));
                    float2 c1 = __ldg((const float2*)(ib + r * 32 + 2));
                    float2 c2 = __ldg((const float2*)(ib + r * 32 + 4));
                    wp[r][0] = pk2(a0.x, c0.x); wp[r][1] = pk2(a0.y, c0.y);
                    wp[r][2] = pk2(a1.x, c1.x); wp[r][3] = pk2(a1.y, c1.y);
                    wp[r][4] = pk2(a2.x, c2.x); wp[r][5] = pk2(a2.y, c2.y);
                }
                const float* wb = w1s + cin * 200 + cg * 3;
                #pragma unroll
                for (int k = 0; k < 25; k++) {
                    int ky = k / 5, kx = k % 5;
                    f32x2_t w0 = dup2(wb[k * 8 + 0]);
                    f32x2_t w1 = dup2(wb[k * 8 + 1]);
                    f32x2_t w2 = dup2(wb[k * 8 + 2]);
                    #pragma unroll
                    for (int q = 0; q < 4; q++) {
                        int qy = q >> 1, qx = q & 1;
                        f32x2_t wv = wp[ky + qy][kx + qx];
                        acc[0][q] = fma2(w0, wv, acc[0][q]);
                        acc[1][q] = fma2(w1, wv, acc[1][q]);
                        acc[2][q] = fma2(w2, wv, acc[2][q]);
                    }
                }
            }
            #pragma unroll
            for (int c = 0; c < 3; c++) {
                int ch = cg * 3 + c;
                float2 q0 = upk(acc[c][0]), q1 = upk(acc[c][1]);
                float2 q2 = upk(acc[c][2]), q3 = upk(acc[c][3]);
                float bb = b1s[ch];
                float2 v;
                v.x = fmaxf(fmaxf(fmaxf(q0.x, q1.x), fmaxf(q2.x, q3.x)) + bb, 0.0f);
                v.y = fmaxf(fmaxf(fmaxf(q0.y, q1.y), fmaxf(q2.y, q3.y)) + bb, 0.0f);
                p1p[(ip * 6 + ch) * 196 + p] = v;
            }
        }
    }
    __syncthreads();

    // ---- conv2 + relu + pool : thread = (img-pair, co-pair, pooled px) ----
    for (int s = tid; s < 800; s += THREADS) {
        int ip = s / 200, r = s % 200;
        int cop = r / 25, p = r % 25;           // cop 0..7 -> channels 2*cop,2*cop+1
        int py = p / 5, px = p % 5;
        int cq = cop >> 1, clb = (cop & 1) * 2;
        f32x2_t acc[2][4];
        #pragma unroll
        for (int c = 0; c < 2; c++)
            acc[c][0] = acc[c][1] = acc[c][2] = acc[c][3] = 0ULL;

        #pragma unroll 1
        for (int cin = 0; cin < 6; cin++) {
            f32x2_t wp[6][6];
            const float2* ibp = p1p + (ip * 6 + cin) * 196 + py * 28 + px * 2;
            #pragma unroll
            for (int rr = 0; rr < 6; rr++) {
                ulonglong2 u0 = *(const ulonglong2*)(ibp + rr * 14);
                ulonglong2 u1 = *(const ulonglong2*)(ibp + rr * 14 + 2);
                ulonglong2 u2 = *(const ulonglong2*)(ibp + rr * 14 + 4);
                wp[rr][0] = u0.x; wp[rr][1] = u0.y;
                wp[rr][2] = u1.x; wp[rr][3] = u1.y;
                wp[rr][4] = u2.x; wp[rr][5] = u2.y;
            }
            const float* wb = w2s + (cq * 6 + cin) * 100 + clb;
            #pragma unroll
            for (int k = 0; k < 25; k++) {
                int ky = k / 5, kx = k % 5;
                f32x2_t w0 = dup2(wb[k * 4 + 0]);
                f32x2_t w1 = dup2(wb[k * 4 + 1]);
                #pragma unroll
                for (int q = 0; q < 4; q++) {
                    int qy = q >> 1, qx = q & 1;
                    f32x2_t wv = wp[ky + qy][kx + qx];
                    acc[0][q] = fma2(w0, wv, acc[0][q]);
                    acc[1][q] = fma2(w1, wv, acc[1][q]);
                }
            }
        }
        #pragma unroll
        for (int c = 0; c < 2; c++) {
            int ch = cop * 2 + c;
            float2 q0 = upk(acc[c][0]), q1 = upk(acc[c][1]);
            float2 q2 = upk(acc[c][2]), q3 = upk(acc[c][3]);
            float bb = b2s[ch];
            float2 v;
            v.x = fmaxf(fmaxf(fmaxf(q0.x, q1.x), fmaxf(q2.x, q3.x)) + bb, 0.0f);
            v.y = fmaxf(fmaxf(fmaxf(q0.y, q1.y), fmaxf(q2.y, q3.y)) + bb, 0.0f);
            h2p[ip * 400 + ch * 25 + p] = v;    // NCHW-flatten order per image
        }
    }
    __syncthreads();

    // ---- fc1: thread = (j-pair 0..59, img-pair 0..3), relu ----
    if (tid < 240) {
        int ip = tid & 3, jp = tid >> 2;
        int j0 = jp * 2;
        const float2* hp = h2p + ip * 400;
        f32x2_t acc0 = 0ULL, acc1 = 0ULL;
        #pragma unroll 4
        for (int k = 0; k < 400; k++) {
            f32x2_t ap = *(const f32x2_t*)(hp + k);
            float2 w = *(const float2*)(g_fw1t + k * 120 + j0);
            acc0 = fma2(dup2(w.x), ap, acc0);
            acc1 = fma2(dup2(w.y), ap, acc1);
        }
        float2 r0 = upk(acc0), r1 = upk(acc1);
        float bb0 = fb1[j0], bb1 = fb1[j0 + 1];
        float2 o0, o1;
        o0.x = fmaxf(r0.x + bb0, 0.0f); o0.y = fmaxf(r0.y + bb0, 0.0f);
        o1.x = fmaxf(r1.x + bb1, 0.0f); o1.y = fmaxf(r1.y + bb1, 0.0f);
        a1p[ip * 120 + j0]     = o0;
        a1p[ip * 120 + j0 + 1] = o1;
    }
    __syncthreads();

    // ---- fc2: thread = (j-pair 0..41, img-pair 0..3), relu ----
    if (tid < 168) {
        int ip = tid & 3, jp = tid >> 2;
        int j0 = jp * 2;
        const float2* hp = a1p + ip * 120;
        f32x2_t acc0 = 0ULL, acc1 = 0ULL;
        #pragma unroll 4
        for (int k = 0; k < 120; k++) {
            f32x2_t ap = *(const f32x2_t*)(hp + k);
            float2 w = *(const float2*)(g_fw2t + k * 84 + j0);
            acc0 = fma2(dup2(w.x), ap, acc0);
            acc1 = fma2(dup2(w.y), ap, acc1);
        }
        float2 r0 = upk(acc0), r1 = upk(acc1);
        float bb0 = fb2[j0], bb1 = fb2[j0 + 1];
        float2 o0, o1;
        o0.x = fmaxf(r0.x + bb0, 0.0f); o0.y = fmaxf(r0.y + bb0, 0.0f);
        o1.x = fmaxf(r1.x + bb1, 0.0f); o1.y = fmaxf(r1.y + bb1, 0.0f);
        a2p[ip * 84 + j0]     = o0;
        a2p[ip * 84 + j0 + 1] = o1;
    }
    __syncthreads();

    // ---- fc3: [84] -> [10] ----
    if (tid < G * 10) {
        int g = tid / 10, j = tid % 10;
        const float* ag = (const float*)(a2p + (g >> 1) * 84);
        int im = g & 1;
        float s0 = 0.f, s1 = 0.f;
        #pragma unroll 6
        for (int k = 0; k < 84; k += 2) {
            s0 = fmaf(ag[k * 2 + im],       g_fw3t[(k)     * 10 + j], s0);
            s1 = fmaf(ag[(k + 1) * 2 + im], g_fw3t[(k + 1) * 10 + j], s1);
        }
        out[(size_t)(img0 + g) * 10 + j] = fb3[j] + s0 + s1;
    }
}

extern "C" void kernel_launch(void* const* d_in, const int* in_sizes, int n_in,
                              void* d_out, int out_size) {
    const float* x   = (const float*)d_in[0];
    const float* w1  = (const float*)d_in[1];
    const float* b1  = (const float*)d_in[2];
    const float* w2  = (const float*)d_in[3];
    const float* b2  = (const float*)d_in[4];
    const float* fw1 = (const float*)d_in[5];
    const float* fb1 = (const float*)d_in[6];
    const float* fw2 = (const float*)d_in[7];
    const float* fb2 = (const float*)d_in[8];
    const float* fw3 = (const float*)d_in[9];
    const float* fb3 = (const float*)d_in[10];
    float* out = (float*)d_out;

    // smem: (4704+1600+480+336)*2 + 600+2400+6+16 = 17262 floats = 69,048 B
    const int smem_floats = (4704 + 1600 + 480 + 336) * 2 + 600 + 2400 + 6 + 16;
    const int smem_bytes = smem_floats * (int)sizeof(float);
    cudaFuncSetAttribute(fused_kernel, cudaFuncAttributeMaxDynamicSharedMemorySize,
                         smem_bytes);

    binarize_kernel<<<5, 256>>>(w1, w2, fw1, fw2, fw3);
    fused_kernel<<<NBLK, THREADS, smem_bytes>>>(x, b1, b2, fb1, fb2, fb3, out);
}